// round 15
// baseline (speedup 1.0000x reference)
#include <cuda_runtime.h>
#include <cuda_fp16.h>
#include <cstdint>
#include <cstddef>

// ---------------------------------------------------------------------------
// GraphConvolution (base sm_103, mma.sync HMMA):
//   e     = H_e @ p^T
//   M1    = (T*diag(e)) @ T^T        lower-tri 256x128 tiles, single-fp16 MMA
//   Bcomb = 0.5*(M1'+1) .* adj_v     fused epilogue -> single fp16, smem-staged
//   HvWT  = (W^T split) @ H_v^T      fp16 2-product (W exact), [OUT_V][N]
//   ret   = Bcomb @ HvWT^T + bias    split-K x2 fp16 mma + fp32 reduce
//   out   = concat(ret, H_e)
// ---------------------------------------------------------------------------

#define N_NODES 4096
#define E_EDGES 8192
#define IN_V    512
#define OUT_V   512
#define IN_E    128

#define KC      64
#define NCHUNK1 (E_EDGES / KC)    // 128
#define NCHUNKF (N_NODES / KC)    // 64
#define NCHUNKH (IN_V / KC)       // 8
#define NTILE1  272               // lower-tri 256x128 tiles

// gemm1 stage: A(Gf 256x64 = 32K) + B(Tf 128x64 = 16K) = 48K, 3 stages.
// Epilogue staging needs 102400 B; mainloop needs 147456 -> take max.
#define G1_STAGE  49152
#define G1_SMEM   147456
// hvw: 2-product stage = 48K x 3
#define H_STAGE   49152
#define H_SMEM    (3 * H_STAGE)
// final: single-product stage = 32K x 4
#define F_STAGE   32768
#define F_SMEM    (4 * F_STAGE)

// Static device scratch
__device__ float g_escale[E_EDGES];
__device__ __half g_Gf [(size_t)N_NODES * E_EDGES];   // 64 MB
__device__ __half g_Tf [(size_t)N_NODES * E_EDGES];   // 64 MB
__device__ __half g_Bf [(size_t)N_NODES * N_NODES];   // 32 MB
__device__ __half g_Hvf[(size_t)N_NODES * IN_V];      // 4 MB
__device__ __half g_WThi[(size_t)OUT_V * IN_V];
__device__ __half g_WTlo[(size_t)OUT_V * IN_V];
__device__ __half g_HvWT[(size_t)OUT_V * N_NODES];    // 4 MB, [n][j]
__device__ float  g_part[2][(size_t)N_NODES * OUT_V]; // 16 MB split-K partials

// ------------------------------ helpers ------------------------------------
__device__ __forceinline__ uint32_t smem_u32(const void* p) {
    uint32_t a;
    asm("{ .reg .u64 t; cvta.to.shared.u64 t, %1; cvt.u32.u64 %0, t; }"
        : "=r"(a) : "l"(p));
    return a;
}
__device__ __forceinline__ uint32_t swz(uint32_t x) { return x ^ ((x >> 3) & 0x70u); }

__device__ __forceinline__ void ldsm_x4(uint32_t& a0, uint32_t& a1,
                                        uint32_t& a2, uint32_t& a3, uint32_t addr) {
    asm volatile("ldmatrix.sync.aligned.m8n8.x4.shared.b16 {%0,%1,%2,%3}, [%4];"
                 : "=r"(a0), "=r"(a1), "=r"(a2), "=r"(a3) : "r"(addr));
}
__device__ __forceinline__ void mma_f16(float* d, const uint32_t* a, const uint32_t* b) {
    asm volatile(
        "mma.sync.aligned.m16n8k16.row.col.f32.f16.f16.f32 "
        "{%0,%1,%2,%3}, {%4,%5,%6,%7}, {%8,%9}, {%0,%1,%2,%3};"
        : "+f"(d[0]), "+f"(d[1]), "+f"(d[2]), "+f"(d[3])
        : "r"(a[0]), "r"(a[1]), "r"(a[2]), "r"(a[3]), "r"(b[0]), "r"(b[1]));
}
__device__ __forceinline__ void hsplit(float v, __half& h, __half& l) {
    h = __float2half(v);
    l = __float2half(v - __half2float(h));
}
__device__ __forceinline__ uint32_t hpack(__half a, __half b) {
    return (uint32_t)__half_as_ushort(a) | ((uint32_t)__half_as_ushort(b) << 16);
}
__device__ __forceinline__ void cpa16(uint32_t dst, const void* src) {
    asm volatile("cp.async.cg.shared.global [%0], [%1], 16;" :: "r"(dst), "l"(src));
}
#define CP_COMMIT() asm volatile("cp.async.commit_group;" ::: "memory")
#define CP_WAIT0()  asm volatile("cp.async.wait_group 0;" ::: "memory")
#define CP_WAIT1()  asm volatile("cp.async.wait_group 1;" ::: "memory")
#define CP_WAIT2()  asm volatile("cp.async.wait_group 2;" ::: "memory")

// ---------------------------------------------------------------------------
// Kernel 1: e[r] = dot(H_e[r,:], p)
// ---------------------------------------------------------------------------
__global__ void escale_kernel(const float* __restrict__ He,
                              const float* __restrict__ p) {
    int warp = threadIdx.x >> 5;
    int lane = threadIdx.x & 31;
    int row  = blockIdx.x * 8 + warp;
    if (row >= E_EDGES) return;
    const float* hr = He + (size_t)row * IN_E;
    float s = 0.f;
#pragma unroll
    for (int i = 0; i < IN_E; i += 32)
        s += hr[i + lane] * p[i + lane];
#pragma unroll
    for (int off = 16; off > 0; off >>= 1)
        s += __shfl_down_sync(0xffffffffu, s, off);
    if (lane == 0) g_escale[row] = s;
}

// ---------------------------------------------------------------------------
// Kernel 1b: Gf = fp16(T*diag(e)); Tf = fp16(T)
// ---------------------------------------------------------------------------
__global__ __launch_bounds__(256)
void convert_kernel(const float* __restrict__ T) {
    unsigned g   = blockIdx.x * 256u + threadIdx.x;
    unsigned row = g >> 11;
    unsigned k4  = (g & 2047u) * 4u;
    size_t base = (size_t)row * E_EDGES + k4;
    float4 t = *(const float4*)(T + base);
    float4 e = *(const float4*)(g_escale + k4);
    uint2 gf = make_uint2(hpack(__float2half(t.x * e.x), __float2half(t.y * e.y)),
                          hpack(__float2half(t.z * e.z), __float2half(t.w * e.w)));
    uint2 tf = make_uint2(hpack(__float2half(t.x), __float2half(t.y)),
                          hpack(__float2half(t.z), __float2half(t.w)));
    *(uint2*)(g_Gf + base) = gf;
    *(uint2*)(g_Tf + base) = tf;
}

// ---------------------------------------------------------------------------
// Kernel 1c: Hvf = fp16(H_v) elementwise
// ---------------------------------------------------------------------------
__global__ __launch_bounds__(256)
void convert_hv_kernel(const float* __restrict__ Hv) {
    unsigned g = blockIdx.x * 256u + threadIdx.x;
    size_t base = (size_t)g * 4;
    float4 v = *(const float4*)(Hv + base);
    *(uint2*)(g_Hvf + base) = make_uint2(hpack(__float2half(v.x), __float2half(v.y)),
                                         hpack(__float2half(v.z), __float2half(v.w)));
}

// ---------------------------------------------------------------------------
// Kernel 1d: WT hi/lo = transposed split of W  ([n][k] = W[k][n])
// ---------------------------------------------------------------------------
__global__ __launch_bounds__(256)
void convert_wt_kernel(const float* __restrict__ W) {
    __shared__ float tile[32][33];
    int tx = threadIdx.x & 31;
    int ty = threadIdx.x >> 5;
    int n0 = blockIdx.x * 32;
    int k0 = blockIdx.y * 32;
#pragma unroll
    for (int i = ty; i < 32; i += 8)
        tile[i][tx] = W[(size_t)(k0 + i) * OUT_V + n0 + tx];
    __syncthreads();
#pragma unroll
    for (int i = ty; i < 32; i += 8) {
        __half h, l;
        hsplit(tile[tx][i], h, l);
        size_t idx = (size_t)(n0 + i) * IN_V + k0 + tx;
        g_WThi[idx] = h;
        g_WTlo[idx] = l;
    }
}

// ---------------------------------------------------------------------------
// Kernel 2: HvWT[n][j] = sum_k W[k][n]*Hv[j][k]   (A = WT split, B = Hvf)
// ---------------------------------------------------------------------------
__global__ __launch_bounds__(256, 1)
void hvw_mma() {
    extern __shared__ char smem[];
    uint32_t sb = smem_u32(smem);
    const int tid  = threadIdx.x;
    const int wid  = tid >> 5;
    const int lane = tid & 31;
    const int wr = wid >> 2, wc = wid & 3;

    const unsigned rowbase = blockIdx.y * 128u;   // n
    const unsigned colbase = blockIdx.x * 128u;   // j

    float acc[4][4][4];
#pragma unroll
    for (int m = 0; m < 4; m++)
#pragma unroll
        for (int n = 0; n < 4; n++)
#pragma unroll
            for (int i = 0; i < 4; i++) acc[m][n][i] = 0.f;

    auto load_chunk = [&](int c, int s) {
        uint32_t sbase = sb + (uint32_t)s * H_STAGE;
        unsigned kbase = (unsigned)c * KC;
#pragma unroll
        for (int i = 0; i < 12; i++) {
            const int arr = i >> 2;
            const int ci  = (i & 3) * 256 + tid;
            const int r   = ci >> 3;
            const int q   = ci & 7;
            const __half* src;
            unsigned grow;
            if (arr == 0)      { src = g_WThi; grow = rowbase + r; }
            else if (arr == 1) { src = g_WTlo; grow = rowbase + r; }
            else               { src = g_Hvf;  grow = colbase + r; }
            cpa16(sbase + (uint32_t)arr * 16384u + swz((uint32_t)(r * 128 + q * 16)),
                  (const void*)(src + (size_t)grow * IN_V + kbase + q * 8));
        }
    };

    load_chunk(0, 0); CP_COMMIT();
    load_chunk(1, 1); CP_COMMIT();

    const int la_row = lane & 15, la_kh = lane >> 4;
    const int gB = lane >> 3, rB = lane & 7, ntO = gB >> 1, khB = gB & 1;

    for (int c = 0; c < NCHUNKH; c++) {
        CP_WAIT1();
        __syncthreads();
        if (c + 2 < NCHUNKH) load_chunk(c + 2, (c + 2) % 3);
        CP_COMMIT();
        uint32_t stage = sb + (uint32_t)(c % 3) * H_STAGE;
        uint32_t aHiB = stage, aLoB = stage + 16384u, bB = stage + 32768u;
#pragma unroll
        for (int ks = 0; ks < 4; ks++) {
            uint32_t ahi[4][4], alo[4][4], bf[4][2];
#pragma unroll
            for (int mt = 0; mt < 4; mt++) {
                uint32_t off = swz((uint32_t)((wr * 64 + mt * 16 + la_row) * 128
                                              + ks * 32 + la_kh * 16));
                ldsm_x4(ahi[mt][0], ahi[mt][1], ahi[mt][2], ahi[mt][3], aHiB + off);
                ldsm_x4(alo[mt][0], alo[mt][1], alo[mt][2], alo[mt][3], aLoB + off);
            }
#pragma unroll
            for (int p = 0; p < 2; p++) {
                uint32_t off = swz((uint32_t)((wc * 32 + (p * 2 + ntO) * 8 + rB) * 128
                                              + ks * 32 + khB * 16));
                ldsm_x4(bf[p * 2][0], bf[p * 2][1], bf[p * 2 + 1][0], bf[p * 2 + 1][1],
                        bB + off);
            }
#pragma unroll
            for (int mt = 0; mt < 4; mt++)
#pragma unroll
                for (int nt = 0; nt < 4; nt++) {
                    mma_f16(acc[mt][nt], ahi[mt], bf[nt]);
                    mma_f16(acc[mt][nt], alo[mt], bf[nt]);
                }
        }
    }

#pragma unroll
    for (int mt = 0; mt < 4; mt++) {
        unsigned r0 = rowbase + wr * 64 + mt * 16 + (lane >> 2);
#pragma unroll
        for (int nt = 0; nt < 4; nt++) {
            unsigned cc = colbase + wc * 32 + nt * 8 + 2 * (lane & 3);
            *(uint32_t*)&g_HvWT[(size_t)r0 * N_NODES + cc] =
                hpack(__float2half(acc[mt][nt][0]), __float2half(acc[mt][nt][1]));
            *(uint32_t*)&g_HvWT[(size_t)(r0 + 8) * N_NODES + cc] =
                hpack(__float2half(acc[mt][nt][2]), __float2half(acc[mt][nt][3]));
        }
    }
}

// ---------------------------------------------------------------------------
// Kernel 3: gemm1 = lower-tri 256x128 tiles of M1 = Gf @ Tf^T (single product)
// 512 threads, 16 warps as 4x4, warp tile 64x32.  KC=64, 3 stages.
// Epilogue: Bcomb fp16, smem-staged coalesced, + mirror.
// ---------------------------------------------------------------------------
__global__ __launch_bounds__(512, 1)
void gemm1_mma(const float* __restrict__ adj_v) {
    extern __shared__ char smem[];
    uint32_t sb = smem_u32(smem);
    const int tid  = threadIdx.x;
    const int wid  = tid >> 5;
    const int lane = tid & 31;
    const int wr   = wid >> 2;        // 0..3 (64-row bands)
    const int wc   = wid & 3;         // 0..3 (32-col bands)

    unsigned l = blockIdx.x;
    unsigned rt = (unsigned)((sqrtf(4.f * (float)l + 1.f) - 1.f) * 0.5f);
    while (rt * rt + rt > l) rt--;
    while ((rt + 1u) * (rt + 1u) + (rt + 1u) <= l) rt++;
    unsigned ct = l - (rt * rt + rt);
    const unsigned rowbase = rt * 256u;
    const unsigned colbase = ct * 128u;
    const bool crossing = (ct >= 2u * rt);

    float acc[4][4][4];
#pragma unroll
    for (int m = 0; m < 4; m++)
#pragma unroll
        for (int n = 0; n < 4; n++)
#pragma unroll
            for (int i = 0; i < 4; i++) acc[m][n][i] = 0.f;

    auto load_chunk = [&](int c, int s) {
        uint32_t sbase = sb + (uint32_t)s * G1_STAGE;
        unsigned kbase = (unsigned)c * KC;
#pragma unroll
        for (int i = 0; i < 4; i++) {
            int slot = i * 512 + tid;
            int r = slot >> 3, q = slot & 7;
            cpa16(sbase + swz((uint32_t)(r * 128 + q * 16)),
                  (const void*)(g_Gf + (size_t)(rowbase + r) * E_EDGES + kbase + q * 8));
        }
#pragma unroll
        for (int i = 0; i < 2; i++) {
            int slot = i * 512 + tid;
            int r = slot >> 3, q = slot & 7;
            cpa16(sbase + 32768u + swz((uint32_t)(r * 128 + q * 16)),
                  (const void*)(g_Tf + (size_t)(colbase + r) * E_EDGES + kbase + q * 8));
        }
    };

    load_chunk(0, 0); CP_COMMIT();
    load_chunk(1, 1); CP_COMMIT();

    const int la_row = lane & 15, la_kh = lane >> 4;
    const int gB = lane >> 3, rB = lane & 7, ntO = gB >> 1, khB = gB & 1;

    for (int c = 0; c < NCHUNK1; c++) {
        CP_WAIT1();
        __syncthreads();
        if (c + 2 < NCHUNK1) load_chunk(c + 2, (c + 2) % 3);
        CP_COMMIT();
        uint32_t stage = sb + (uint32_t)(c % 3) * G1_STAGE;
        uint32_t aB = stage, bB = stage + 32768u;
#pragma unroll
        for (int ks = 0; ks < 4; ks++) {
            uint32_t af[4][4], bf[4][2];
#pragma unroll
            for (int mt = 0; mt < 4; mt++) {
                uint32_t off = swz((uint32_t)((wr * 64 + mt * 16 + la_row) * 128
                                              + ks * 32 + la_kh * 16));
                ldsm_x4(af[mt][0], af[mt][1], af[mt][2], af[mt][3], aB + off);
            }
#pragma unroll
            for (int p = 0; p < 2; p++) {
                uint32_t off = swz((uint32_t)((wc * 32 + (p * 2 + ntO) * 8 + rB) * 128
                                              + ks * 32 + khB * 16));
                ldsm_x4(bf[p * 2][0], bf[p * 2][1], bf[p * 2 + 1][0], bf[p * 2 + 1][1],
                        bB + off);
            }
#pragma unroll
            for (int mt = 0; mt < 4; mt++)
#pragma unroll
                for (int nt = 0; nt < 4; nt++)
                    mma_f16(acc[mt][nt], af[mt], bf[nt]);
        }
    }
    __syncthreads();   // smem about to be reused by the epilogue

    if (!crossing) {
        // -------- Phase 1: direct tile, staged -> coalesced STG --------
#pragma unroll
        for (int mt = 0; mt < 4; mt++) {
            int rl0 = wr * 64 + mt * 16 + (lane >> 2);
            int rl1 = rl0 + 8;
            unsigned r0 = rowbase + rl0, r1 = rowbase + rl1;
#pragma unroll
            for (int nt = 0; nt < 4; nt++) {
                int cl = wc * 32 + nt * 8 + 2 * (lane & 3);
                unsigned cc = colbase + cl;
                float2 a0 = *(const float2*)&adj_v[(size_t)r0 * N_NODES + cc];
                float2 a1 = *(const float2*)&adj_v[(size_t)r1 * N_NODES + cc];
                *(uint32_t*)(smem + rl0 * 272 + cl * 2) =
                    hpack(__float2half(0.5f * (acc[mt][nt][0] + 1.f) * a0.x),
                          __float2half(0.5f * (acc[mt][nt][1] + 1.f) * a0.y));
                *(uint32_t*)(smem + rl1 * 272 + cl * 2) =
                    hpack(__float2half(0.5f * (acc[mt][nt][2] + 1.f) * a1.x),
                          __float2half(0.5f * (acc[mt][nt][3] + 1.f) * a1.y));
            }
        }
        __syncthreads();
#pragma unroll
        for (int it = 0; it < 8; it++) {
            int slot = it * 512 + tid;
            int r = slot >> 4, q = slot & 15;
            uint4 v = *(uint4*)(smem + r * 272 + q * 16);
            *(uint4*)&g_Bf[(size_t)(rowbase + r) * N_NODES + colbase + q * 8] = v;
        }
        __syncthreads();

        // -------- Phase 2: mirror, two 128-row halves --------
#pragma unroll
        for (int h = 0; h < 2; h++) {
#pragma unroll
            for (int it = 0; it < 8; it++) {
                int slot = it * 512 + tid;
                int cl = slot >> 5, q = slot & 31;
                float4 v = *(const float4*)&adj_v[(size_t)(colbase + cl) * N_NODES
                                                  + rowbase + h * 128 + q * 4];
                *(float4*)(smem + cl * 528 + q * 16) = v;
            }
            __syncthreads();
            if ((wr >> 1) == h) {
#pragma unroll
                for (int mt = 0; mt < 4; mt++)
#pragma unroll
                    for (int nt = 0; nt < 4; nt++)
#pragma unroll
                        for (int e = 0; e < 4; e++) {
                            int rl = (wr & 1) * 64 + mt * 16 + (lane >> 2) + (e >> 1) * 8;
                            int cl = wc * 32 + nt * 8 + 2 * (lane & 3) + (e & 1);
                            float adjv = *(float*)(smem + cl * 528 + rl * 4);
                            *(__half*)(smem + 67584 + cl * 272 + rl * 2) =
                                __float2half(0.5f * (acc[mt][nt][e] + 1.f) * adjv);
                        }
            }
            __syncthreads();
#pragma unroll
            for (int it = 0; it < 4; it++) {
                int slot = it * 512 + tid;
                int cl = slot >> 4, q = slot & 15;
                uint4 v = *(uint4*)(smem + 67584 + cl * 272 + q * 16);
                *(uint4*)&g_Bf[(size_t)(colbase + cl) * N_NODES
                               + rowbase + h * 128 + q * 8] = v;
            }
            __syncthreads();
        }
    } else {
        // crossing tiles: predicated scalar path (writes each element once)
#pragma unroll
        for (int mt = 0; mt < 4; mt++) {
            unsigned r0 = rowbase + wr * 64 + mt * 16 + (lane >> 2);
#pragma unroll
            for (int nt = 0; nt < 4; nt++) {
                unsigned cc = colbase + wc * 32 + nt * 8 + 2 * (lane & 3);
#pragma unroll
                for (int e = 0; e < 4; e++) {
                    unsigned r = r0 + (e >> 1) * 8;
                    unsigned c2 = cc + (e & 1);
                    float a = acc[mt][nt][e];
                    if (r >= c2) {
                        float av = adj_v[(size_t)r * N_NODES + c2];
                        float bv = (r == c2) ? av : 0.5f * (a + 1.f) * av;
                        g_Bf[(size_t)r * N_NODES + c2] = __float2half(bv);
                    }
                    if (r > c2) {
                        float bm = 0.5f * (a + 1.f) * adj_v[(size_t)c2 * N_NODES + r];
                        g_Bf[(size_t)c2 * N_NODES + r] = __float2half(bm);
                    }
                }
            }
        }
    }
}

// ---------------------------------------------------------------------------
// Kernel 4: split-K x2 final GEMM: g_part[z] = Bf[:, zK/2:(z+1)K/2] @ HvWT^T
// grid (4, 32, 2), 128x128 tile, 32 chunks per CTA.
// ---------------------------------------------------------------------------
__global__ __launch_bounds__(256, 1)
void final_mma() {
    extern __shared__ char smem[];
    uint32_t sb = smem_u32(smem);
    const int tid  = threadIdx.x;
    const int wid  = tid >> 5;
    const int lane = tid & 31;
    const int wr = wid >> 2, wc = wid & 3;

    const unsigned rowbase = blockIdx.y * 128u;   // i
    const unsigned colbase = blockIdx.x * 128u;   // n
    const unsigned z = blockIdx.z;
    const int c0 = (int)z * (NCHUNKF / 2);
    const int c1 = c0 + (NCHUNKF / 2);
    float* part = g_part[z];

    float acc[4][4][4];
#pragma unroll
    for (int m = 0; m < 4; m++)
#pragma unroll
        for (int n = 0; n < 4; n++)
#pragma unroll
            for (int i = 0; i < 4; i++) acc[m][n][i] = 0.f;

    auto load_chunk = [&](int c, int s) {
        uint32_t sbase = sb + (uint32_t)s * F_STAGE;
        unsigned kbase = (unsigned)c * KC;
#pragma unroll
        for (int i = 0; i < 8; i++) {
            const int arr = i >> 2;                 // 0:A 1:B
            const int ci  = (i & 3) * 256 + tid;
            const int r   = ci >> 3;
            const int q   = ci & 7;
            const __half* src = (arr == 0) ? g_Bf : g_HvWT;
            unsigned grow = (arr == 0) ? (rowbase + r) : (colbase + r);
            cpa16(sbase + (uint32_t)arr * 16384u + swz((uint32_t)(r * 128 + q * 16)),
                  (const void*)(src + (size_t)grow * N_NODES + kbase + q * 8));
        }
    };

    load_chunk(c0, 0); CP_COMMIT();
    load_chunk(c0 + 1, 1); CP_COMMIT();
    load_chunk(c0 + 2, 2); CP_COMMIT();

    const int la_row = lane & 15, la_kh = lane >> 4;
    const int gB = lane >> 3, rB = lane & 7, ntO = gB >> 1, khB = gB & 1;

    for (int c = c0; c < c1; c++) {
        CP_WAIT2();
        __syncthreads();
        if (c + 3 < c1) load_chunk(c + 3, (c + 3) & 3);
        CP_COMMIT();
        uint32_t stage = sb + (uint32_t)(c & 3) * F_STAGE;
        uint32_t aB = stage, bB = stage + 16384u;
#pragma unroll
        for (int ks = 0; ks < 4; ks++) {
            uint32_t af[4][4], bf[4][2];
#pragma unroll
            for (int mt = 0; mt < 4; mt++) {
                uint32_t off = swz((uint32_t)((wr * 64 + mt * 16 + la_row) * 128
                                              + ks * 32 + la_kh * 16));
                ldsm_x4(af[mt][0], af[mt][1], af[mt][2], af[mt][3], aB + off);
            }
#pragma unroll
            for (int p = 0; p < 2; p++) {
                uint32_t off = swz((uint32_t)((wc * 32 + (p * 2 + ntO) * 8 + rB) * 128
                                              + ks * 32 + khB * 16));
                ldsm_x4(bf[p * 2][0], bf[p * 2][1], bf[p * 2 + 1][0], bf[p * 2 + 1][1],
                        bB + off);
            }
#pragma unroll
            for (int mt = 0; mt < 4; mt++)
#pragma unroll
                for (int nt = 0; nt < 4; nt++)
                    mma_f16(acc[mt][nt], af[mt], bf[nt]);
        }
    }

#pragma unroll
    for (int mt = 0; mt < 4; mt++) {
        unsigned r0 = rowbase + wr * 64 + mt * 16 + (lane >> 2);
#pragma unroll
        for (int nt = 0; nt < 4; nt++) {
            unsigned cc = colbase + wc * 32 + nt * 8 + 2 * (lane & 3);
            *(float2*)&part[(size_t)r0 * OUT_V + cc] =
                make_float2(acc[mt][nt][0], acc[mt][nt][1]);
            *(float2*)&part[(size_t)(r0 + 8) * OUT_V + cc] =
                make_float2(acc[mt][nt][2], acc[mt][nt][3]);
        }
    }
}

// ---------------------------------------------------------------------------
// Kernel 5: out = part0 + part1 + bias
// ---------------------------------------------------------------------------
__global__ __launch_bounds__(256)
void reduce_kernel(const float* __restrict__ bias, float* __restrict__ out) {
    unsigned g = blockIdx.x * 256u + threadIdx.x;
    size_t base = (size_t)g * 4;
    float4 a = *(const float4*)(g_part[0] + base);
    float4 b = *(const float4*)(g_part[1] + base);
    float4 bv = *(const float4*)(bias + (base & (OUT_V - 1)));
    float4 r = make_float4(a.x + b.x + bv.x, a.y + b.y + bv.y,
                           a.z + b.z + bv.z, a.w + b.w + bv.w);
    *(float4*)(out + base) = r;
}

// ---------------------------------------------------------------------------
extern "C" void kernel_launch(void* const* d_in, const int* in_sizes, int n_in,
                              void* d_out, int out_size) {
    const float* H_v   = (const float*)d_in[0];
    const float* H_e   = (const float*)d_in[1];
    // d_in[2] = adj_e : unused by the reference
    const float* adj_v = (const float*)d_in[3];
    const float* T     = (const float*)d_in[4];
    const float* W     = (const float*)d_in[5];
    const float* p     = (const float*)d_in[6];
    const float* bias  = (const float*)d_in[7];
    float* out = (float*)d_out;

    static cudaStream_t s1 = nullptr;
    static cudaEvent_t evRoot = nullptr, evJoin = nullptr;
    static bool init_done = false;
    if (!init_done) {
        cudaFuncSetAttribute(gemm1_mma, cudaFuncAttributeMaxDynamicSharedMemorySize, G1_SMEM);
        cudaFuncSetAttribute(hvw_mma,   cudaFuncAttributeMaxDynamicSharedMemorySize, H_SMEM);
        cudaFuncSetAttribute(final_mma, cudaFuncAttributeMaxDynamicSharedMemorySize, F_SMEM);
        cudaStreamCreateWithFlags(&s1, cudaStreamNonBlocking);
        cudaEventCreateWithFlags(&evRoot, cudaEventDisableTiming);
        cudaEventCreateWithFlags(&evJoin, cudaEventDisableTiming);
        init_done = true;
    }

    // Fork side chain onto s1 (rooted in the captured stream via evRoot).
    cudaEventRecord(evRoot, 0);
    cudaStreamWaitEvent(s1, evRoot, 0);

    // s1: converts for the HvW path, HvWT GEMM, and the H_e passthrough.
    convert_hv_kernel<<<(N_NODES * (IN_V / 4)) / 256, 256, 0, s1>>>(H_v);
    convert_wt_kernel<<<dim3(OUT_V / 32, IN_V / 32), 256, 0, s1>>>(W);
    hvw_mma<<<dim3(N_NODES / 128, OUT_V / 128), 256, H_SMEM, s1>>>();
    int he_elems = in_sizes[1];
    cudaMemcpyAsync(out + ((size_t)out_size - he_elems), H_e,
                    (size_t)he_elems * sizeof(float),
                    cudaMemcpyDeviceToDevice, s1);
    cudaEventRecord(evJoin, s1);

    // s0 (critical chain): e -> Gf/Tf -> gemm1 (Bcomb)
    escale_kernel<<<E_EDGES / 8, 256>>>(H_e, p);
    convert_kernel<<<(N_NODES * (E_EDGES / 4)) / 256, 256>>>(T);
    gemm1_mma<<<NTILE1, 512, G1_SMEM>>>(adj_v);

    // join, then split-K final GEMM + reduce
    cudaStreamWaitEvent(0, evJoin, 0);
    final_mma<<<dim3(OUT_V / 128, N_NODES / 128, 2), 256, F_SMEM>>>();
    reduce_kernel<<<(N_NODES * OUT_V / 4) / 256, 256>>>(bias, out);
}

// round 16
// speedup vs baseline: 1.0311x; 1.0311x over previous
#include <cuda_runtime.h>
#include <cuda_fp16.h>
#include <cstdint>
#include <cstddef>

// ---------------------------------------------------------------------------
// GraphConvolution (base sm_103, mma.sync HMMA):
//   e     = H_e @ p^T
//   M1    = (T*diag(e)) @ T^T        lower-tri 256x128 tiles, single-fp16 MMA
//   Bcomb = 0.5*(M1'+1) .* adj_v     fused epilogue -> single fp16, smem-staged
//   HvWT  = (W^T split) @ H_v^T      fp16 2-product (W exact), [OUT_V][N]
//   ret   = Bcomb @ HvWT^T + bias    single-product fp16 mma -> out
//   out   = concat(ret, H_e)
// R16: revert R15 (split-K, 3-stage gemm1) to R14 config; gemm1 tile order
// remapped so the 32 slow diagonal-crossing tiles run in wave 1 (tail trim).
// ---------------------------------------------------------------------------

#define N_NODES 4096
#define E_EDGES 8192
#define IN_V    512
#define OUT_V   512
#define IN_E    128

#define KC      64
#define NCHUNK1 (E_EDGES / KC)    // 128
#define NCHUNKF (N_NODES / KC)    // 64
#define NCHUNKH (IN_V / KC)       // 8
#define NTILE1  272               // lower-tri 256x128 tiles

// gemm1 stage: A(Gf 256x64 = 32K) + B(Tf 128x64 = 16K) = 48K, 2 stages.
// Epilogue staging needs 102400 B -> allocate that.
#define G1_STAGE  49152
#define G1_SMEM   102400
// hvw: 2-product stage = 48K x 3
#define H_STAGE   49152
#define H_SMEM    (3 * H_STAGE)
// final: single-product stage = 32K x 4
#define F_STAGE   32768
#define F_SMEM    (4 * F_STAGE)

// Static device scratch
__device__ float g_escale[E_EDGES];
__device__ __half g_Gf [(size_t)N_NODES * E_EDGES];   // 64 MB
__device__ __half g_Tf [(size_t)N_NODES * E_EDGES];   // 64 MB
__device__ __half g_Bf [(size_t)N_NODES * N_NODES];   // 32 MB
__device__ __half g_Hvf[(size_t)N_NODES * IN_V];      // 4 MB
__device__ __half g_WThi[(size_t)OUT_V * IN_V];
__device__ __half g_WTlo[(size_t)OUT_V * IN_V];
__device__ __half g_HvWT[(size_t)OUT_V * N_NODES];    // 4 MB, [n][j]

// ------------------------------ helpers ------------------------------------
__device__ __forceinline__ uint32_t smem_u32(const void* p) {
    uint32_t a;
    asm("{ .reg .u64 t; cvta.to.shared.u64 t, %1; cvt.u32.u64 %0, t; }"
        : "=r"(a) : "l"(p));
    return a;
}
__device__ __forceinline__ uint32_t swz(uint32_t x) { return x ^ ((x >> 3) & 0x70u); }

__device__ __forceinline__ void ldsm_x4(uint32_t& a0, uint32_t& a1,
                                        uint32_t& a2, uint32_t& a3, uint32_t addr) {
    asm volatile("ldmatrix.sync.aligned.m8n8.x4.shared.b16 {%0,%1,%2,%3}, [%4];"
                 : "=r"(a0), "=r"(a1), "=r"(a2), "=r"(a3) : "r"(addr));
}
__device__ __forceinline__ void mma_f16(float* d, const uint32_t* a, const uint32_t* b) {
    asm volatile(
        "mma.sync.aligned.m16n8k16.row.col.f32.f16.f16.f32 "
        "{%0,%1,%2,%3}, {%4,%5,%6,%7}, {%8,%9}, {%0,%1,%2,%3};"
        : "+f"(d[0]), "+f"(d[1]), "+f"(d[2]), "+f"(d[3])
        : "r"(a[0]), "r"(a[1]), "r"(a[2]), "r"(a[3]), "r"(b[0]), "r"(b[1]));
}
__device__ __forceinline__ void hsplit(float v, __half& h, __half& l) {
    h = __float2half(v);
    l = __float2half(v - __half2float(h));
}
__device__ __forceinline__ uint32_t hpack(__half a, __half b) {
    return (uint32_t)__half_as_ushort(a) | ((uint32_t)__half_as_ushort(b) << 16);
}
__device__ __forceinline__ void cpa16(uint32_t dst, const void* src) {
    asm volatile("cp.async.cg.shared.global [%0], [%1], 16;" :: "r"(dst), "l"(src));
}
#define CP_COMMIT() asm volatile("cp.async.commit_group;" ::: "memory")
#define CP_WAIT0()  asm volatile("cp.async.wait_group 0;" ::: "memory")
#define CP_WAIT1()  asm volatile("cp.async.wait_group 1;" ::: "memory")
#define CP_WAIT2()  asm volatile("cp.async.wait_group 2;" ::: "memory")

// ---------------------------------------------------------------------------
// Kernel 1: e[r] = dot(H_e[r,:], p)
// ---------------------------------------------------------------------------
__global__ void escale_kernel(const float* __restrict__ He,
                              const float* __restrict__ p) {
    int warp = threadIdx.x >> 5;
    int lane = threadIdx.x & 31;
    int row  = blockIdx.x * 8 + warp;
    if (row >= E_EDGES) return;
    const float* hr = He + (size_t)row * IN_E;
    float s = 0.f;
#pragma unroll
    for (int i = 0; i < IN_E; i += 32)
        s += hr[i + lane] * p[i + lane];
#pragma unroll
    for (int off = 16; off > 0; off >>= 1)
        s += __shfl_down_sync(0xffffffffu, s, off);
    if (lane == 0) g_escale[row] = s;
}

// ---------------------------------------------------------------------------
// Kernel 1b: Gf = fp16(T*diag(e)); Tf = fp16(T)
// ---------------------------------------------------------------------------
__global__ __launch_bounds__(256)
void convert_kernel(const float* __restrict__ T) {
    unsigned g   = blockIdx.x * 256u + threadIdx.x;
    unsigned row = g >> 11;
    unsigned k4  = (g & 2047u) * 4u;
    size_t base = (size_t)row * E_EDGES + k4;
    float4 t = *(const float4*)(T + base);
    float4 e = *(const float4*)(g_escale + k4);
    uint2 gf = make_uint2(hpack(__float2half(t.x * e.x), __float2half(t.y * e.y)),
                          hpack(__float2half(t.z * e.z), __float2half(t.w * e.w)));
    uint2 tf = make_uint2(hpack(__float2half(t.x), __float2half(t.y)),
                          hpack(__float2half(t.z), __float2half(t.w)));
    *(uint2*)(g_Gf + base) = gf;
    *(uint2*)(g_Tf + base) = tf;
}

// ---------------------------------------------------------------------------
// Kernel 1c: Hvf = fp16(H_v) elementwise
// ---------------------------------------------------------------------------
__global__ __launch_bounds__(256)
void convert_hv_kernel(const float* __restrict__ Hv) {
    unsigned g = blockIdx.x * 256u + threadIdx.x;
    size_t base = (size_t)g * 4;
    float4 v = *(const float4*)(Hv + base);
    *(uint2*)(g_Hvf + base) = make_uint2(hpack(__float2half(v.x), __float2half(v.y)),
                                         hpack(__float2half(v.z), __float2half(v.w)));
}

// ---------------------------------------------------------------------------
// Kernel 1d: WT hi/lo = transposed split of W  ([n][k] = W[k][n])
// ---------------------------------------------------------------------------
__global__ __launch_bounds__(256)
void convert_wt_kernel(const float* __restrict__ W) {
    __shared__ float tile[32][33];
    int tx = threadIdx.x & 31;
    int ty = threadIdx.x >> 5;
    int n0 = blockIdx.x * 32;
    int k0 = blockIdx.y * 32;
#pragma unroll
    for (int i = ty; i < 32; i += 8)
        tile[i][tx] = W[(size_t)(k0 + i) * OUT_V + n0 + tx];
    __syncthreads();
#pragma unroll
    for (int i = ty; i < 32; i += 8) {
        __half h, l;
        hsplit(tile[tx][i], h, l);
        size_t idx = (size_t)(n0 + i) * IN_V + k0 + tx;
        g_WThi[idx] = h;
        g_WTlo[idx] = l;
    }
}

// ---------------------------------------------------------------------------
// Kernel 2: HvWT[n][j] = sum_k W[k][n]*Hv[j][k]   (A = WT split, B = Hvf)
// ---------------------------------------------------------------------------
__global__ __launch_bounds__(256, 1)
void hvw_mma() {
    extern __shared__ char smem[];
    uint32_t sb = smem_u32(smem);
    const int tid  = threadIdx.x;
    const int wid  = tid >> 5;
    const int lane = tid & 31;
    const int wr = wid >> 2, wc = wid & 3;

    const unsigned rowbase = blockIdx.y * 128u;   // n
    const unsigned colbase = blockIdx.x * 128u;   // j

    float acc[4][4][4];
#pragma unroll
    for (int m = 0; m < 4; m++)
#pragma unroll
        for (int n = 0; n < 4; n++)
#pragma unroll
            for (int i = 0; i < 4; i++) acc[m][n][i] = 0.f;

    auto load_chunk = [&](int c, int s) {
        uint32_t sbase = sb + (uint32_t)s * H_STAGE;
        unsigned kbase = (unsigned)c * KC;
#pragma unroll
        for (int i = 0; i < 12; i++) {
            const int arr = i >> 2;
            const int ci  = (i & 3) * 256 + tid;
            const int r   = ci >> 3;
            const int q   = ci & 7;
            const __half* src;
            unsigned grow;
            if (arr == 0)      { src = g_WThi; grow = rowbase + r; }
            else if (arr == 1) { src = g_WTlo; grow = rowbase + r; }
            else               { src = g_Hvf;  grow = colbase + r; }
            cpa16(sbase + (uint32_t)arr * 16384u + swz((uint32_t)(r * 128 + q * 16)),
                  (const void*)(src + (size_t)grow * IN_V + kbase + q * 8));
        }
    };

    load_chunk(0, 0); CP_COMMIT();
    load_chunk(1, 1); CP_COMMIT();

    const int la_row = lane & 15, la_kh = lane >> 4;
    const int gB = lane >> 3, rB = lane & 7, ntO = gB >> 1, khB = gB & 1;

    for (int c = 0; c < NCHUNKH; c++) {
        CP_WAIT1();
        __syncthreads();
        if (c + 2 < NCHUNKH) load_chunk(c + 2, (c + 2) % 3);
        CP_COMMIT();
        uint32_t stage = sb + (uint32_t)(c % 3) * H_STAGE;
        uint32_t aHiB = stage, aLoB = stage + 16384u, bB = stage + 32768u;
#pragma unroll
        for (int ks = 0; ks < 4; ks++) {
            uint32_t ahi[4][4], alo[4][4], bf[4][2];
#pragma unroll
            for (int mt = 0; mt < 4; mt++) {
                uint32_t off = swz((uint32_t)((wr * 64 + mt * 16 + la_row) * 128
                                              + ks * 32 + la_kh * 16));
                ldsm_x4(ahi[mt][0], ahi[mt][1], ahi[mt][2], ahi[mt][3], aHiB + off);
                ldsm_x4(alo[mt][0], alo[mt][1], alo[mt][2], alo[mt][3], aLoB + off);
            }
#pragma unroll
            for (int p = 0; p < 2; p++) {
                uint32_t off = swz((uint32_t)((wc * 32 + (p * 2 + ntO) * 8 + rB) * 128
                                              + ks * 32 + khB * 16));
                ldsm_x4(bf[p * 2][0], bf[p * 2][1], bf[p * 2 + 1][0], bf[p * 2 + 1][1],
                        bB + off);
            }
#pragma unroll
            for (int mt = 0; mt < 4; mt++)
#pragma unroll
                for (int nt = 0; nt < 4; nt++) {
                    mma_f16(acc[mt][nt], ahi[mt], bf[nt]);
                    mma_f16(acc[mt][nt], alo[mt], bf[nt]);
                }
        }
    }

#pragma unroll
    for (int mt = 0; mt < 4; mt++) {
        unsigned r0 = rowbase + wr * 64 + mt * 16 + (lane >> 2);
#pragma unroll
        for (int nt = 0; nt < 4; nt++) {
            unsigned cc = colbase + wc * 32 + nt * 8 + 2 * (lane & 3);
            *(uint32_t*)&g_HvWT[(size_t)r0 * N_NODES + cc] =
                hpack(__float2half(acc[mt][nt][0]), __float2half(acc[mt][nt][1]));
            *(uint32_t*)&g_HvWT[(size_t)(r0 + 8) * N_NODES + cc] =
                hpack(__float2half(acc[mt][nt][2]), __float2half(acc[mt][nt][3]));
        }
    }
}

// ---------------------------------------------------------------------------
// Kernel 3: gemm1 = lower-tri 256x128 tiles of M1 = Gf @ Tf^T (single product)
// 512 threads, 16 warps as 4x4, warp tile 64x32.  KC=64, 2 stages.
// Tile order: 32 diagonal-crossing tiles first (slow scalar epilogue in
// wave 1), then interior tiles.  Epilogue: Bcomb fp16 smem-staged + mirror.
// ---------------------------------------------------------------------------
__global__ __launch_bounds__(512, 1)
void gemm1_mma(const float* __restrict__ adj_v) {
    extern __shared__ char smem[];
    uint32_t sb = smem_u32(smem);
    const int tid  = threadIdx.x;
    const int wid  = tid >> 5;
    const int lane = tid & 31;
    const int wr   = wid >> 2;        // 0..3 (64-row bands)
    const int wc   = wid & 3;         // 0..3 (32-col bands)

    // Remapped tile id: l < 32 -> crossing tiles (ct = 2rt or 2rt+1);
    // l >= 32 -> interior tiles (ct < 2rt), cumulative rt^2 - rt.
    unsigned l = blockIdx.x;
    unsigned rt, ct;
    bool crossing;
    if (l < 32u) {
        rt = l >> 1;
        ct = 2u * rt + (l & 1u);
        crossing = true;
    } else {
        unsigned lp = l - 32u;
        rt = (unsigned)((1.f + sqrtf(4.f * (float)lp + 1.f)) * 0.5f);
        while (rt * (rt - 1u) > lp) rt--;
        while (rt * (rt + 1u) <= lp) rt++;
        ct = lp - rt * (rt - 1u);
        crossing = false;
    }
    const unsigned rowbase = rt * 256u;
    const unsigned colbase = ct * 128u;

    float acc[4][4][4];
#pragma unroll
    for (int m = 0; m < 4; m++)
#pragma unroll
        for (int n = 0; n < 4; n++)
#pragma unroll
            for (int i = 0; i < 4; i++) acc[m][n][i] = 0.f;

    auto load_chunk = [&](int c, int s) {
        uint32_t sbase = sb + (uint32_t)s * G1_STAGE;
        unsigned kbase = (unsigned)c * KC;
#pragma unroll
        for (int i = 0; i < 4; i++) {
            int slot = i * 512 + tid;
            int r = slot >> 3, q = slot & 7;
            cpa16(sbase + swz((uint32_t)(r * 128 + q * 16)),
                  (const void*)(g_Gf + (size_t)(rowbase + r) * E_EDGES + kbase + q * 8));
        }
#pragma unroll
        for (int i = 0; i < 2; i++) {
            int slot = i * 512 + tid;
            int r = slot >> 3, q = slot & 7;
            cpa16(sbase + 32768u + swz((uint32_t)(r * 128 + q * 16)),
                  (const void*)(g_Tf + (size_t)(colbase + r) * E_EDGES + kbase + q * 8));
        }
    };

    load_chunk(0, 0); CP_COMMIT();

    const int la_row = lane & 15, la_kh = lane >> 4;
    const int gB = lane >> 3, rB = lane & 7, ntO = gB >> 1, khB = gB & 1;

    for (int c = 0; c < NCHUNK1; c++) {
        CP_WAIT0();
        __syncthreads();
        if (c + 1 < NCHUNK1) load_chunk(c + 1, (c + 1) & 1);
        CP_COMMIT();
        uint32_t stage = sb + (uint32_t)(c & 1) * G1_STAGE;
        uint32_t aB = stage, bB = stage + 32768u;
#pragma unroll
        for (int ks = 0; ks < 4; ks++) {
            uint32_t af[4][4], bf[4][2];
#pragma unroll
            for (int mt = 0; mt < 4; mt++) {
                uint32_t off = swz((uint32_t)((wr * 64 + mt * 16 + la_row) * 128
                                              + ks * 32 + la_kh * 16));
                ldsm_x4(af[mt][0], af[mt][1], af[mt][2], af[mt][3], aB + off);
            }
#pragma unroll
            for (int p = 0; p < 2; p++) {
                uint32_t off = swz((uint32_t)((wc * 32 + (p * 2 + ntO) * 8 + rB) * 128
                                              + ks * 32 + khB * 16));
                ldsm_x4(bf[p * 2][0], bf[p * 2][1], bf[p * 2 + 1][0], bf[p * 2 + 1][1],
                        bB + off);
            }
#pragma unroll
            for (int mt = 0; mt < 4; mt++)
#pragma unroll
                for (int nt = 0; nt < 4; nt++)
                    mma_f16(acc[mt][nt], af[mt], bf[nt]);
        }
    }
    __syncthreads();   // smem about to be reused by the epilogue

    if (!crossing) {
        // -------- Phase 1: direct tile, staged -> coalesced STG --------
#pragma unroll
        for (int mt = 0; mt < 4; mt++) {
            int rl0 = wr * 64 + mt * 16 + (lane >> 2);
            int rl1 = rl0 + 8;
            unsigned r0 = rowbase + rl0, r1 = rowbase + rl1;
#pragma unroll
            for (int nt = 0; nt < 4; nt++) {
                int cl = wc * 32 + nt * 8 + 2 * (lane & 3);
                unsigned cc = colbase + cl;
                float2 a0 = *(const float2*)&adj_v[(size_t)r0 * N_NODES + cc];
                float2 a1 = *(const float2*)&adj_v[(size_t)r1 * N_NODES + cc];
                *(uint32_t*)(smem + rl0 * 272 + cl * 2) =
                    hpack(__float2half(0.5f * (acc[mt][nt][0] + 1.f) * a0.x),
                          __float2half(0.5f * (acc[mt][nt][1] + 1.f) * a0.y));
                *(uint32_t*)(smem + rl1 * 272 + cl * 2) =
                    hpack(__float2half(0.5f * (acc[mt][nt][2] + 1.f) * a1.x),
                          __float2half(0.5f * (acc[mt][nt][3] + 1.f) * a1.y));
            }
        }
        __syncthreads();
#pragma unroll
        for (int it = 0; it < 8; it++) {
            int slot = it * 512 + tid;
            int r = slot >> 4, q = slot & 15;
            uint4 v = *(uint4*)(smem + r * 272 + q * 16);
            *(uint4*)&g_Bf[(size_t)(rowbase + r) * N_NODES + colbase + q * 8] = v;
        }
        __syncthreads();

        // -------- Phase 2: mirror, two 128-row halves --------
#pragma unroll
        for (int h = 0; h < 2; h++) {
#pragma unroll
            for (int it = 0; it < 8; it++) {
                int slot = it * 512 + tid;
                int cl = slot >> 5, q = slot & 31;
                float4 v = *(const float4*)&adj_v[(size_t)(colbase + cl) * N_NODES
                                                  + rowbase + h * 128 + q * 4];
                *(float4*)(smem + cl * 528 + q * 16) = v;
            }
            __syncthreads();
            if ((wr >> 1) == h) {
#pragma unroll
                for (int mt = 0; mt < 4; mt++)
#pragma unroll
                    for (int nt = 0; nt < 4; nt++)
#pragma unroll
                        for (int e = 0; e < 4; e++) {
                            int rl = (wr & 1) * 64 + mt * 16 + (lane >> 2) + (e >> 1) * 8;
                            int cl = wc * 32 + nt * 8 + 2 * (lane & 3) + (e & 1);
                            float adjv = *(float*)(smem + cl * 528 + rl * 4);
                            *(__half*)(smem + 67584 + cl * 272 + rl * 2) =
                                __float2half(0.5f * (acc[mt][nt][e] + 1.f) * adjv);
                        }
            }
            __syncthreads();
#pragma unroll
            for (int it = 0; it < 4; it++) {
                int slot = it * 512 + tid;
                int cl = slot >> 4, q = slot & 15;
                uint4 v = *(uint4*)(smem + 67584 + cl * 272 + q * 16);
                *(uint4*)&g_Bf[(size_t)(colbase + cl) * N_NODES
                               + rowbase + h * 128 + q * 8] = v;
            }
            __syncthreads();
        }
    } else {
        // crossing tiles: predicated scalar path (writes each element once)
#pragma unroll
        for (int mt = 0; mt < 4; mt++) {
            unsigned r0 = rowbase + wr * 64 + mt * 16 + (lane >> 2);
#pragma unroll
            for (int nt = 0; nt < 4; nt++) {
                unsigned cc = colbase + wc * 32 + nt * 8 + 2 * (lane & 3);
#pragma unroll
                for (int e = 0; e < 4; e++) {
                    unsigned r = r0 + (e >> 1) * 8;
                    unsigned c2 = cc + (e & 1);
                    float a = acc[mt][nt][e];
                    if (r >= c2) {
                        float av = adj_v[(size_t)r * N_NODES + c2];
                        float bv = (r == c2) ? av : 0.5f * (a + 1.f) * av;
                        g_Bf[(size_t)r * N_NODES + c2] = __float2half(bv);
                    }
                    if (r > c2) {
                        float bm = 0.5f * (a + 1.f) * adj_v[(size_t)c2 * N_NODES + r];
                        g_Bf[(size_t)c2 * N_NODES + r] = __float2half(bm);
                    }
                }
            }
        }
    }
}

// ---------------------------------------------------------------------------
// Kernel 4: ret = Bf @ HvWT^T + bias  (single product).  M=4096,N=512,K=4096.
// ---------------------------------------------------------------------------
__global__ __launch_bounds__(256, 1)
void final_mma(const float* __restrict__ bias, float* __restrict__ out) {
    extern __shared__ char smem[];
    uint32_t sb = smem_u32(smem);
    const int tid  = threadIdx.x;
    const int wid  = tid >> 5;
    const int lane = tid & 31;
    const int wr = wid >> 2, wc = wid & 3;

    const unsigned rowbase = blockIdx.y * 128u;   // i
    const unsigned colbase = blockIdx.x * 128u;   // n

    float acc[4][4][4];
#pragma unroll
    for (int m = 0; m < 4; m++)
#pragma unroll
        for (int n = 0; n < 4; n++)
#pragma unroll
            for (int i = 0; i < 4; i++) acc[m][n][i] = 0.f;

    auto load_chunk = [&](int c, int s) {
        uint32_t sbase = sb + (uint32_t)s * F_STAGE;
        unsigned kbase = (unsigned)c * KC;
#pragma unroll
        for (int i = 0; i < 8; i++) {
            const int arr = i >> 2;                 // 0:A 1:B
            const int ci  = (i & 3) * 256 + tid;
            const int r   = ci >> 3;
            const int q   = ci & 7;
            const __half* src = (arr == 0) ? g_Bf : g_HvWT;
            unsigned grow = (arr == 0) ? (rowbase + r) : (colbase + r);
            cpa16(sbase + (uint32_t)arr * 16384u + swz((uint32_t)(r * 128 + q * 16)),
                  (const void*)(src + (size_t)grow * N_NODES + kbase + q * 8));
        }
    };

    load_chunk(0, 0); CP_COMMIT();
    load_chunk(1, 1); CP_COMMIT();
    load_chunk(2, 2); CP_COMMIT();

    const int la_row = lane & 15, la_kh = lane >> 4;
    const int gB = lane >> 3, rB = lane & 7, ntO = gB >> 1, khB = gB & 1;

    for (int c = 0; c < NCHUNKF; c++) {
        CP_WAIT2();
        __syncthreads();
        if (c + 3 < NCHUNKF) load_chunk(c + 3, (c + 3) & 3);
        CP_COMMIT();
        uint32_t stage = sb + (uint32_t)(c & 3) * F_STAGE;
        uint32_t aB = stage, bB = stage + 16384u;
#pragma unroll
        for (int ks = 0; ks < 4; ks++) {
            uint32_t af[4][4], bf[4][2];
#pragma unroll
            for (int mt = 0; mt < 4; mt++) {
                uint32_t off = swz((uint32_t)((wr * 64 + mt * 16 + la_row) * 128
                                              + ks * 32 + la_kh * 16));
                ldsm_x4(af[mt][0], af[mt][1], af[mt][2], af[mt][3], aB + off);
            }
#pragma unroll
            for (int p = 0; p < 2; p++) {
                uint32_t off = swz((uint32_t)((wc * 32 + (p * 2 + ntO) * 8 + rB) * 128
                                              + ks * 32 + khB * 16));
                ldsm_x4(bf[p * 2][0], bf[p * 2][1], bf[p * 2 + 1][0], bf[p * 2 + 1][1],
                        bB + off);
            }
#pragma unroll
            for (int mt = 0; mt < 4; mt++)
#pragma unroll
                for (int nt = 0; nt < 4; nt++)
                    mma_f16(acc[mt][nt], af[mt], bf[nt]);
        }
    }

#pragma unroll
    for (int mt = 0; mt < 4; mt++) {
        unsigned r0 = rowbase + wr * 64 + mt * 16 + (lane >> 2);
#pragma unroll
        for (int nt = 0; nt < 4; nt++) {
            unsigned cc = colbase + wc * 32 + nt * 8 + 2 * (lane & 3);
            float2 bv = *(const float2*)&bias[cc];
            *(float2*)&out[(size_t)r0 * OUT_V + cc] =
                make_float2(acc[mt][nt][0] + bv.x, acc[mt][nt][1] + bv.y);
            *(float2*)&out[(size_t)(r0 + 8) * OUT_V + cc] =
                make_float2(acc[mt][nt][2] + bv.x, acc[mt][nt][3] + bv.y);
        }
    }
}

// ---------------------------------------------------------------------------
extern "C" void kernel_launch(void* const* d_in, const int* in_sizes, int n_in,
                              void* d_out, int out_size) {
    const float* H_v   = (const float*)d_in[0];
    const float* H_e   = (const float*)d_in[1];
    // d_in[2] = adj_e : unused by the reference
    const float* adj_v = (const float*)d_in[3];
    const float* T     = (const float*)d_in[4];
    const float* W     = (const float*)d_in[5];
    const float* p     = (const float*)d_in[6];
    const float* bias  = (const float*)d_in[7];
    float* out = (float*)d_out;

    static cudaStream_t s1 = nullptr;
    static cudaEvent_t evRoot = nullptr, evJoin = nullptr;
    static bool init_done = false;
    if (!init_done) {
        cudaFuncSetAttribute(gemm1_mma, cudaFuncAttributeMaxDynamicSharedMemorySize, G1_SMEM);
        cudaFuncSetAttribute(hvw_mma,   cudaFuncAttributeMaxDynamicSharedMemorySize, H_SMEM);
        cudaFuncSetAttribute(final_mma, cudaFuncAttributeMaxDynamicSharedMemorySize, F_SMEM);
        cudaStreamCreateWithFlags(&s1, cudaStreamNonBlocking);
        cudaEventCreateWithFlags(&evRoot, cudaEventDisableTiming);
        cudaEventCreateWithFlags(&evJoin, cudaEventDisableTiming);
        init_done = true;
    }

    // Fork side chain onto s1 (rooted in the captured stream via evRoot).
    cudaEventRecord(evRoot, 0);
    cudaStreamWaitEvent(s1, evRoot, 0);

    // s1: converts for the HvW path, HvWT GEMM, and the H_e passthrough.
    convert_hv_kernel<<<(N_NODES * (IN_V / 4)) / 256, 256, 0, s1>>>(H_v);
    convert_wt_kernel<<<dim3(OUT_V / 32, IN_V / 32), 256, 0, s1>>>(W);
    hvw_mma<<<dim3(N_NODES / 128, OUT_V / 128), 256, H_SMEM, s1>>>();
    int he_elems = in_sizes[1];
    cudaMemcpyAsync(out + ((size_t)out_size - he_elems), H_e,
                    (size_t)he_elems * sizeof(float),
                    cudaMemcpyDeviceToDevice, s1);
    cudaEventRecord(evJoin, s1);

    // s0 (critical chain): e -> Gf/Tf -> gemm1 (Bcomb)
    escale_kernel<<<E_EDGES / 8, 256>>>(H_e, p);
    convert_kernel<<<(N_NODES * (E_EDGES / 4)) / 256, 256>>>(T);
    gemm1_mma<<<NTILE1, 512, G1_SMEM>>>(adj_v);

    // join, then final GEMM
    cudaStreamWaitEvent(0, evJoin, 0);
    final_mma<<<dim3(OUT_V / 128, N_NODES / 128), 256, F_SMEM>>>(bias, out);
}

// round 17
// speedup vs baseline: 1.0478x; 1.0162x over previous
#include <cuda_runtime.h>
#include <cuda_fp16.h>
#include <cstdint>
#include <cstddef>

// ---------------------------------------------------------------------------
// GraphConvolution (base sm_103, mma.sync HMMA):
//   e     = H_e @ p^T
//   M1    = (T*diag(e)) @ T^T        lower-tri 256x128 tiles, single-fp16 MMA
//   Bcomb = 0.5*(M1'+1) .* adj_v     fused epilogue -> single fp16, smem-staged
//   HvWT  = (W^T split) @ H_v^T      fp16 2-product (W exact), [OUT_V][N]
//   ret   = Bcomb @ HvWT^T + bias    single-product fp16 mma -> out
//   out   = concat(ret, H_e)
// R17: gemm1 back to R14 mapping (R16 reorder regressed); final_mma retiled
// to 64x128 (256 CTAs, 1.7 waves) for occupancy/latency hiding.
// ---------------------------------------------------------------------------

#define N_NODES 4096
#define E_EDGES 8192
#define IN_V    512
#define OUT_V   512
#define IN_E    128

#define KC      64
#define NCHUNK1 (E_EDGES / KC)    // 128
#define NCHUNKF (N_NODES / KC)    // 64
#define NCHUNKH (IN_V / KC)       // 8
#define NTILE1  272               // lower-tri 256x128 tiles

// gemm1 stage: A(Gf 256x64 = 32K) + B(Tf 128x64 = 16K) = 48K, 2 stages.
// Epilogue staging needs 102400 B -> allocate that.
#define G1_STAGE  49152
#define G1_SMEM   102400
// hvw: 2-product stage = 48K x 3
#define H_STAGE   49152
#define H_SMEM    (3 * H_STAGE)
// final: 64x128 tile stage = A(8K) + B(16K) = 24K, 4 stages
#define F_STAGE   24576
#define F_SMEM    (4 * F_STAGE)

// Static device scratch
__device__ float g_escale[E_EDGES];
__device__ __half g_Gf [(size_t)N_NODES * E_EDGES];   // 64 MB
__device__ __half g_Tf [(size_t)N_NODES * E_EDGES];   // 64 MB
__device__ __half g_Bf [(size_t)N_NODES * N_NODES];   // 32 MB
__device__ __half g_Hvf[(size_t)N_NODES * IN_V];      // 4 MB
__device__ __half g_WThi[(size_t)OUT_V * IN_V];
__device__ __half g_WTlo[(size_t)OUT_V * IN_V];
__device__ __half g_HvWT[(size_t)OUT_V * N_NODES];    // 4 MB, [n][j]

// ------------------------------ helpers ------------------------------------
__device__ __forceinline__ uint32_t smem_u32(const void* p) {
    uint32_t a;
    asm("{ .reg .u64 t; cvta.to.shared.u64 t, %1; cvt.u32.u64 %0, t; }"
        : "=r"(a) : "l"(p));
    return a;
}
__device__ __forceinline__ uint32_t swz(uint32_t x) { return x ^ ((x >> 3) & 0x70u); }

__device__ __forceinline__ void ldsm_x4(uint32_t& a0, uint32_t& a1,
                                        uint32_t& a2, uint32_t& a3, uint32_t addr) {
    asm volatile("ldmatrix.sync.aligned.m8n8.x4.shared.b16 {%0,%1,%2,%3}, [%4];"
                 : "=r"(a0), "=r"(a1), "=r"(a2), "=r"(a3) : "r"(addr));
}
__device__ __forceinline__ void mma_f16(float* d, const uint32_t* a, const uint32_t* b) {
    asm volatile(
        "mma.sync.aligned.m16n8k16.row.col.f32.f16.f16.f32 "
        "{%0,%1,%2,%3}, {%4,%5,%6,%7}, {%8,%9}, {%0,%1,%2,%3};"
        : "+f"(d[0]), "+f"(d[1]), "+f"(d[2]), "+f"(d[3])
        : "r"(a[0]), "r"(a[1]), "r"(a[2]), "r"(a[3]), "r"(b[0]), "r"(b[1]));
}
__device__ __forceinline__ void hsplit(float v, __half& h, __half& l) {
    h = __float2half(v);
    l = __float2half(v - __half2float(h));
}
__device__ __forceinline__ uint32_t hpack(__half a, __half b) {
    return (uint32_t)__half_as_ushort(a) | ((uint32_t)__half_as_ushort(b) << 16);
}
__device__ __forceinline__ void cpa16(uint32_t dst, const void* src) {
    asm volatile("cp.async.cg.shared.global [%0], [%1], 16;" :: "r"(dst), "l"(src));
}
#define CP_COMMIT() asm volatile("cp.async.commit_group;" ::: "memory")
#define CP_WAIT0()  asm volatile("cp.async.wait_group 0;" ::: "memory")
#define CP_WAIT1()  asm volatile("cp.async.wait_group 1;" ::: "memory")
#define CP_WAIT2()  asm volatile("cp.async.wait_group 2;" ::: "memory")

// ---------------------------------------------------------------------------
// Kernel 1: e[r] = dot(H_e[r,:], p)
// ---------------------------------------------------------------------------
__global__ void escale_kernel(const float* __restrict__ He,
                              const float* __restrict__ p) {
    int warp = threadIdx.x >> 5;
    int lane = threadIdx.x & 31;
    int row  = blockIdx.x * 8 + warp;
    if (row >= E_EDGES) return;
    const float* hr = He + (size_t)row * IN_E;
    float s = 0.f;
#pragma unroll
    for (int i = 0; i < IN_E; i += 32)
        s += hr[i + lane] * p[i + lane];
#pragma unroll
    for (int off = 16; off > 0; off >>= 1)
        s += __shfl_down_sync(0xffffffffu, s, off);
    if (lane == 0) g_escale[row] = s;
}

// ---------------------------------------------------------------------------
// Kernel 1b: Gf = fp16(T*diag(e)); Tf = fp16(T)
// ---------------------------------------------------------------------------
__global__ __launch_bounds__(256)
void convert_kernel(const float* __restrict__ T) {
    unsigned g   = blockIdx.x * 256u + threadIdx.x;
    unsigned row = g >> 11;
    unsigned k4  = (g & 2047u) * 4u;
    size_t base = (size_t)row * E_EDGES + k4;
    float4 t = *(const float4*)(T + base);
    float4 e = *(const float4*)(g_escale + k4);
    uint2 gf = make_uint2(hpack(__float2half(t.x * e.x), __float2half(t.y * e.y)),
                          hpack(__float2half(t.z * e.z), __float2half(t.w * e.w)));
    uint2 tf = make_uint2(hpack(__float2half(t.x), __float2half(t.y)),
                          hpack(__float2half(t.z), __float2half(t.w)));
    *(uint2*)(g_Gf + base) = gf;
    *(uint2*)(g_Tf + base) = tf;
}

// ---------------------------------------------------------------------------
// Kernel 1c: Hvf = fp16(H_v) elementwise
// ---------------------------------------------------------------------------
__global__ __launch_bounds__(256)
void convert_hv_kernel(const float* __restrict__ Hv) {
    unsigned g = blockIdx.x * 256u + threadIdx.x;
    size_t base = (size_t)g * 4;
    float4 v = *(const float4*)(Hv + base);
    *(uint2*)(g_Hvf + base) = make_uint2(hpack(__float2half(v.x), __float2half(v.y)),
                                         hpack(__float2half(v.z), __float2half(v.w)));
}

// ---------------------------------------------------------------------------
// Kernel 1d: WT hi/lo = transposed split of W  ([n][k] = W[k][n])
// ---------------------------------------------------------------------------
__global__ __launch_bounds__(256)
void convert_wt_kernel(const float* __restrict__ W) {
    __shared__ float tile[32][33];
    int tx = threadIdx.x & 31;
    int ty = threadIdx.x >> 5;
    int n0 = blockIdx.x * 32;
    int k0 = blockIdx.y * 32;
#pragma unroll
    for (int i = ty; i < 32; i += 8)
        tile[i][tx] = W[(size_t)(k0 + i) * OUT_V + n0 + tx];
    __syncthreads();
#pragma unroll
    for (int i = ty; i < 32; i += 8) {
        __half h, l;
        hsplit(tile[tx][i], h, l);
        size_t idx = (size_t)(n0 + i) * IN_V + k0 + tx;
        g_WThi[idx] = h;
        g_WTlo[idx] = l;
    }
}

// ---------------------------------------------------------------------------
// Kernel 2: HvWT[n][j] = sum_k W[k][n]*Hv[j][k]   (A = WT split, B = Hvf)
// ---------------------------------------------------------------------------
__global__ __launch_bounds__(256, 1)
void hvw_mma() {
    extern __shared__ char smem[];
    uint32_t sb = smem_u32(smem);
    const int tid  = threadIdx.x;
    const int wid  = tid >> 5;
    const int lane = tid & 31;
    const int wr = wid >> 2, wc = wid & 3;

    const unsigned rowbase = blockIdx.y * 128u;   // n
    const unsigned colbase = blockIdx.x * 128u;   // j

    float acc[4][4][4];
#pragma unroll
    for (int m = 0; m < 4; m++)
#pragma unroll
        for (int n = 0; n < 4; n++)
#pragma unroll
            for (int i = 0; i < 4; i++) acc[m][n][i] = 0.f;

    auto load_chunk = [&](int c, int s) {
        uint32_t sbase = sb + (uint32_t)s * H_STAGE;
        unsigned kbase = (unsigned)c * KC;
#pragma unroll
        for (int i = 0; i < 12; i++) {
            const int arr = i >> 2;
            const int ci  = (i & 3) * 256 + tid;
            const int r   = ci >> 3;
            const int q   = ci & 7;
            const __half* src;
            unsigned grow;
            if (arr == 0)      { src = g_WThi; grow = rowbase + r; }
            else if (arr == 1) { src = g_WTlo; grow = rowbase + r; }
            else               { src = g_Hvf;  grow = colbase + r; }
            cpa16(sbase + (uint32_t)arr * 16384u + swz((uint32_t)(r * 128 + q * 16)),
                  (const void*)(src + (size_t)grow * IN_V + kbase + q * 8));
        }
    };

    load_chunk(0, 0); CP_COMMIT();
    load_chunk(1, 1); CP_COMMIT();

    const int la_row = lane & 15, la_kh = lane >> 4;
    const int gB = lane >> 3, rB = lane & 7, ntO = gB >> 1, khB = gB & 1;

    for (int c = 0; c < NCHUNKH; c++) {
        CP_WAIT1();
        __syncthreads();
        if (c + 2 < NCHUNKH) load_chunk(c + 2, (c + 2) % 3);
        CP_COMMIT();
        uint32_t stage = sb + (uint32_t)(c % 3) * H_STAGE;
        uint32_t aHiB = stage, aLoB = stage + 16384u, bB = stage + 32768u;
#pragma unroll
        for (int ks = 0; ks < 4; ks++) {
            uint32_t ahi[4][4], alo[4][4], bf[4][2];
#pragma unroll
            for (int mt = 0; mt < 4; mt++) {
                uint32_t off = swz((uint32_t)((wr * 64 + mt * 16 + la_row) * 128
                                              + ks * 32 + la_kh * 16));
                ldsm_x4(ahi[mt][0], ahi[mt][1], ahi[mt][2], ahi[mt][3], aHiB + off);
                ldsm_x4(alo[mt][0], alo[mt][1], alo[mt][2], alo[mt][3], aLoB + off);
            }
#pragma unroll
            for (int p = 0; p < 2; p++) {
                uint32_t off = swz((uint32_t)((wc * 32 + (p * 2 + ntO) * 8 + rB) * 128
                                              + ks * 32 + khB * 16));
                ldsm_x4(bf[p * 2][0], bf[p * 2][1], bf[p * 2 + 1][0], bf[p * 2 + 1][1],
                        bB + off);
            }
#pragma unroll
            for (int mt = 0; mt < 4; mt++)
#pragma unroll
                for (int nt = 0; nt < 4; nt++) {
                    mma_f16(acc[mt][nt], ahi[mt], bf[nt]);
                    mma_f16(acc[mt][nt], alo[mt], bf[nt]);
                }
        }
    }

#pragma unroll
    for (int mt = 0; mt < 4; mt++) {
        unsigned r0 = rowbase + wr * 64 + mt * 16 + (lane >> 2);
#pragma unroll
        for (int nt = 0; nt < 4; nt++) {
            unsigned cc = colbase + wc * 32 + nt * 8 + 2 * (lane & 3);
            *(uint32_t*)&g_HvWT[(size_t)r0 * N_NODES + cc] =
                hpack(__float2half(acc[mt][nt][0]), __float2half(acc[mt][nt][1]));
            *(uint32_t*)&g_HvWT[(size_t)(r0 + 8) * N_NODES + cc] =
                hpack(__float2half(acc[mt][nt][2]), __float2half(acc[mt][nt][3]));
        }
    }
}

// ---------------------------------------------------------------------------
// Kernel 3: gemm1 = lower-tri 256x128 tiles of M1 = Gf @ Tf^T (single product)
// 512 threads, 16 warps as 4x4, warp tile 64x32.  KC=64, 2 stages.
// Epilogue: Bcomb fp16, smem-staged coalesced, + mirror.  (R14 mapping)
// ---------------------------------------------------------------------------
__global__ __launch_bounds__(512, 1)
void gemm1_mma(const float* __restrict__ adj_v) {
    extern __shared__ char smem[];
    uint32_t sb = smem_u32(smem);
    const int tid  = threadIdx.x;
    const int wid  = tid >> 5;
    const int lane = tid & 31;
    const int wr   = wid >> 2;        // 0..3 (64-row bands)
    const int wc   = wid & 3;         // 0..3 (32-col bands)

    unsigned l = blockIdx.x;
    unsigned rt = (unsigned)((sqrtf(4.f * (float)l + 1.f) - 1.f) * 0.5f);
    while (rt * rt + rt > l) rt--;
    while ((rt + 1u) * (rt + 1u) + (rt + 1u) <= l) rt++;
    unsigned ct = l - (rt * rt + rt);
    const unsigned rowbase = rt * 256u;
    const unsigned colbase = ct * 128u;
    const bool crossing = (ct >= 2u * rt);

    float acc[4][4][4];
#pragma unroll
    for (int m = 0; m < 4; m++)
#pragma unroll
        for (int n = 0; n < 4; n++)
#pragma unroll
            for (int i = 0; i < 4; i++) acc[m][n][i] = 0.f;

    auto load_chunk = [&](int c, int s) {
        uint32_t sbase = sb + (uint32_t)s * G1_STAGE;
        unsigned kbase = (unsigned)c * KC;
#pragma unroll
        for (int i = 0; i < 4; i++) {
            int slot = i * 512 + tid;
            int r = slot >> 3, q = slot & 7;
            cpa16(sbase + swz((uint32_t)(r * 128 + q * 16)),
                  (const void*)(g_Gf + (size_t)(rowbase + r) * E_EDGES + kbase + q * 8));
        }
#pragma unroll
        for (int i = 0; i < 2; i++) {
            int slot = i * 512 + tid;
            int r = slot >> 3, q = slot & 7;
            cpa16(sbase + 32768u + swz((uint32_t)(r * 128 + q * 16)),
                  (const void*)(g_Tf + (size_t)(colbase + r) * E_EDGES + kbase + q * 8));
        }
    };

    load_chunk(0, 0); CP_COMMIT();

    const int la_row = lane & 15, la_kh = lane >> 4;
    const int gB = lane >> 3, rB = lane & 7, ntO = gB >> 1, khB = gB & 1;

    for (int c = 0; c < NCHUNK1; c++) {
        CP_WAIT0();
        __syncthreads();
        if (c + 1 < NCHUNK1) load_chunk(c + 1, (c + 1) & 1);
        CP_COMMIT();
        uint32_t stage = sb + (uint32_t)(c & 1) * G1_STAGE;
        uint32_t aB = stage, bB = stage + 32768u;
#pragma unroll
        for (int ks = 0; ks < 4; ks++) {
            uint32_t af[4][4], bf[4][2];
#pragma unroll
            for (int mt = 0; mt < 4; mt++) {
                uint32_t off = swz((uint32_t)((wr * 64 + mt * 16 + la_row) * 128
                                              + ks * 32 + la_kh * 16));
                ldsm_x4(af[mt][0], af[mt][1], af[mt][2], af[mt][3], aB + off);
            }
#pragma unroll
            for (int p = 0; p < 2; p++) {
                uint32_t off = swz((uint32_t)((wc * 32 + (p * 2 + ntO) * 8 + rB) * 128
                                              + ks * 32 + khB * 16));
                ldsm_x4(bf[p * 2][0], bf[p * 2][1], bf[p * 2 + 1][0], bf[p * 2 + 1][1],
                        bB + off);
            }
#pragma unroll
            for (int mt = 0; mt < 4; mt++)
#pragma unroll
                for (int nt = 0; nt < 4; nt++)
                    mma_f16(acc[mt][nt], af[mt], bf[nt]);
        }
    }
    __syncthreads();   // smem about to be reused by the epilogue

    if (!crossing) {
        // -------- Phase 1: direct tile, staged -> coalesced STG --------
#pragma unroll
        for (int mt = 0; mt < 4; mt++) {
            int rl0 = wr * 64 + mt * 16 + (lane >> 2);
            int rl1 = rl0 + 8;
            unsigned r0 = rowbase + rl0, r1 = rowbase + rl1;
#pragma unroll
            for (int nt = 0; nt < 4; nt++) {
                int cl = wc * 32 + nt * 8 + 2 * (lane & 3);
                unsigned cc = colbase + cl;
                float2 a0 = *(const float2*)&adj_v[(size_t)r0 * N_NODES + cc];
                float2 a1 = *(const float2*)&adj_v[(size_t)r1 * N_NODES + cc];
                *(uint32_t*)(smem + rl0 * 272 + cl * 2) =
                    hpack(__float2half(0.5f * (acc[mt][nt][0] + 1.f) * a0.x),
                          __float2half(0.5f * (acc[mt][nt][1] + 1.f) * a0.y));
                *(uint32_t*)(smem + rl1 * 272 + cl * 2) =
                    hpack(__float2half(0.5f * (acc[mt][nt][2] + 1.f) * a1.x),
                          __float2half(0.5f * (acc[mt][nt][3] + 1.f) * a1.y));
            }
        }
        __syncthreads();
#pragma unroll
        for (int it = 0; it < 8; it++) {
            int slot = it * 512 + tid;
            int r = slot >> 4, q = slot & 15;
            uint4 v = *(uint4*)(smem + r * 272 + q * 16);
            *(uint4*)&g_Bf[(size_t)(rowbase + r) * N_NODES + colbase + q * 8] = v;
        }
        __syncthreads();

        // -------- Phase 2: mirror, two 128-row halves --------
#pragma unroll
        for (int h = 0; h < 2; h++) {
#pragma unroll
            for (int it = 0; it < 8; it++) {
                int slot = it * 512 + tid;
                int cl = slot >> 5, q = slot & 31;
                float4 v = *(const float4*)&adj_v[(size_t)(colbase + cl) * N_NODES
                                                  + rowbase + h * 128 + q * 4];
                *(float4*)(smem + cl * 528 + q * 16) = v;
            }
            __syncthreads();
            if ((wr >> 1) == h) {
#pragma unroll
                for (int mt = 0; mt < 4; mt++)
#pragma unroll
                    for (int nt = 0; nt < 4; nt++)
#pragma unroll
                        for (int e = 0; e < 4; e++) {
                            int rl = (wr & 1) * 64 + mt * 16 + (lane >> 2) + (e >> 1) * 8;
                            int cl = wc * 32 + nt * 8 + 2 * (lane & 3) + (e & 1);
                            float adjv = *(float*)(smem + cl * 528 + rl * 4);
                            *(__half*)(smem + 67584 + cl * 272 + rl * 2) =
                                __float2half(0.5f * (acc[mt][nt][e] + 1.f) * adjv);
                        }
            }
            __syncthreads();
#pragma unroll
            for (int it = 0; it < 4; it++) {
                int slot = it * 512 + tid;
                int cl = slot >> 4, q = slot & 15;
                uint4 v = *(uint4*)(smem + 67584 + cl * 272 + q * 16);
                *(uint4*)&g_Bf[(size_t)(colbase + cl) * N_NODES
                               + rowbase + h * 128 + q * 8] = v;
            }
            __syncthreads();
        }
    } else {
        // crossing tiles: predicated scalar path (writes each element once)
#pragma unroll
        for (int mt = 0; mt < 4; mt++) {
            unsigned r0 = rowbase + wr * 64 + mt * 16 + (lane >> 2);
#pragma unroll
            for (int nt = 0; nt < 4; nt++) {
                unsigned cc = colbase + wc * 32 + nt * 8 + 2 * (lane & 3);
#pragma unroll
                for (int e = 0; e < 4; e++) {
                    unsigned r = r0 + (e >> 1) * 8;
                    unsigned c2 = cc + (e & 1);
                    float a = acc[mt][nt][e];
                    if (r >= c2) {
                        float av = adj_v[(size_t)r * N_NODES + c2];
                        float bv = (r == c2) ? av : 0.5f * (a + 1.f) * av;
                        g_Bf[(size_t)r * N_NODES + c2] = __float2half(bv);
                    }
                    if (r > c2) {
                        float bm = 0.5f * (a + 1.f) * adj_v[(size_t)c2 * N_NODES + r];
                        g_Bf[(size_t)c2 * N_NODES + r] = __float2half(bm);
                    }
                }
            }
        }
    }
}

// ---------------------------------------------------------------------------
// Kernel 4: ret = Bf @ HvWT^T + bias  (single product).  M=4096,N=512,K=4096.
// 64x128 output tiles -> grid (4, 64) = 256 CTAs for full-chip occupancy.
// 8 warps as 2x4, warp tile 32x32.
// ---------------------------------------------------------------------------
__global__ __launch_bounds__(256, 1)
void final_mma(const float* __restrict__ bias, float* __restrict__ out) {
    extern __shared__ char smem[];
    uint32_t sb = smem_u32(smem);
    const int tid  = threadIdx.x;
    const int wid  = tid >> 5;
    const int lane = tid & 31;
    const int wr = wid >> 2;          // 0..1 (32-row bands)
    const int wc = wid & 3;           // 0..3 (32-col bands)

    const unsigned rowbase = blockIdx.y * 64u;    // i
    const unsigned colbase = blockIdx.x * 128u;   // n

    float acc[2][4][4];
#pragma unroll
    for (int m = 0; m < 2; m++)
#pragma unroll
        for (int n = 0; n < 4; n++)
#pragma unroll
            for (int i = 0; i < 4; i++) acc[m][n][i] = 0.f;

    auto load_chunk = [&](int c, int s) {
        uint32_t sbase = sb + (uint32_t)s * F_STAGE;
        unsigned kbase = (unsigned)c * KC;
        // A (Bf): 64 rows x 64 cols = 512 16B slots, 2 per thread
#pragma unroll
        for (int i = 0; i < 2; i++) {
            int slot = i * 256 + tid;
            int r = slot >> 3, q = slot & 7;
            cpa16(sbase + swz((uint32_t)(r * 128 + q * 16)),
                  (const void*)(g_Bf + (size_t)(rowbase + r) * N_NODES + kbase + q * 8));
        }
        // B (HvWT): 128 rows x 64 cols = 1024 slots, 4 per thread
#pragma unroll
        for (int i = 0; i < 4; i++) {
            int slot = i * 256 + tid;
            int r = slot >> 3, q = slot & 7;
            cpa16(sbase + 8192u + swz((uint32_t)(r * 128 + q * 16)),
                  (const void*)(g_HvWT + (size_t)(colbase + r) * N_NODES + kbase + q * 8));
        }
    };

    load_chunk(0, 0); CP_COMMIT();
    load_chunk(1, 1); CP_COMMIT();
    load_chunk(2, 2); CP_COMMIT();

    const int la_row = lane & 15, la_kh = lane >> 4;
    const int gB = lane >> 3, rB = lane & 7, ntO = gB >> 1, khB = gB & 1;

    for (int c = 0; c < NCHUNKF; c++) {
        CP_WAIT2();
        __syncthreads();
        if (c + 3 < NCHUNKF) load_chunk(c + 3, (c + 3) & 3);
        CP_COMMIT();
        uint32_t stage = sb + (uint32_t)(c & 3) * F_STAGE;
        uint32_t aB = stage, bB = stage + 8192u;
#pragma unroll
        for (int ks = 0; ks < 4; ks++) {
            uint32_t af[2][4], bf[4][2];
#pragma unroll
            for (int mt = 0; mt < 2; mt++) {
                uint32_t off = swz((uint32_t)((wr * 32 + mt * 16 + la_row) * 128
                                              + ks * 32 + la_kh * 16));
                ldsm_x4(af[mt][0], af[mt][1], af[mt][2], af[mt][3], aB + off);
            }
#pragma unroll
            for (int p = 0; p < 2; p++) {
                uint32_t off = swz((uint32_t)((wc * 32 + (p * 2 + ntO) * 8 + rB) * 128
                                              + ks * 32 + khB * 16));
                ldsm_x4(bf[p * 2][0], bf[p * 2][1], bf[p * 2 + 1][0], bf[p * 2 + 1][1],
                        bB + off);
            }
#pragma unroll
            for (int mt = 0; mt < 2; mt++)
#pragma unroll
                for (int nt = 0; nt < 4; nt++)
                    mma_f16(acc[mt][nt], af[mt], bf[nt]);
        }
    }

#pragma unroll
    for (int mt = 0; mt < 2; mt++) {
        unsigned r0 = rowbase + wr * 32 + mt * 16 + (lane >> 2);
#pragma unroll
        for (int nt = 0; nt < 4; nt++) {
            unsigned cc = colbase + wc * 32 + nt * 8 + 2 * (lane & 3);
            float2 bv = *(const float2*)&bias[cc];
            *(float2*)&out[(size_t)r0 * OUT_V + cc] =
                make_float2(acc[mt][nt][0] + bv.x, acc[mt][nt][1] + bv.y);
            *(float2*)&out[(size_t)(r0 + 8) * OUT_V + cc] =
                make_float2(acc[mt][nt][2] + bv.x, acc[mt][nt][3] + bv.y);
        }
    }
}

// ---------------------------------------------------------------------------
extern "C" void kernel_launch(void* const* d_in, const int* in_sizes, int n_in,
                              void* d_out, int out_size) {
    const float* H_v   = (const float*)d_in[0];
    const float* H_e   = (const float*)d_in[1];
    // d_in[2] = adj_e : unused by the reference
    const float* adj_v = (const float*)d_in[3];
    const float* T     = (const float*)d_in[4];
    const float* W     = (const float*)d_in[5];
    const float* p     = (const float*)d_in[6];
    const float* bias  = (const float*)d_in[7];
    float* out = (float*)d_out;

    static cudaStream_t s1 = nullptr;
    static cudaEvent_t evRoot = nullptr, evJoin = nullptr;
    static bool init_done = false;
    if (!init_done) {
        cudaFuncSetAttribute(gemm1_mma, cudaFuncAttributeMaxDynamicSharedMemorySize, G1_SMEM);
        cudaFuncSetAttribute(hvw_mma,   cudaFuncAttributeMaxDynamicSharedMemorySize, H_SMEM);
        cudaFuncSetAttribute(final_mma, cudaFuncAttributeMaxDynamicSharedMemorySize, F_SMEM);
        cudaStreamCreateWithFlags(&s1, cudaStreamNonBlocking);
        cudaEventCreateWithFlags(&evRoot, cudaEventDisableTiming);
        cudaEventCreateWithFlags(&evJoin, cudaEventDisableTiming);
        init_done = true;
    }

    // Fork side chain onto s1 (rooted in the captured stream via evRoot).
    cudaEventRecord(evRoot, 0);
    cudaStreamWaitEvent(s1, evRoot, 0);

    // s1: converts for the HvW path, HvWT GEMM, and the H_e passthrough.
    convert_hv_kernel<<<(N_NODES * (IN_V / 4)) / 256, 256, 0, s1>>>(H_v);
    convert_wt_kernel<<<dim3(OUT_V / 32, IN_V / 32), 256, 0, s1>>>(W);
    hvw_mma<<<dim3(N_NODES / 128, OUT_V / 128), 256, H_SMEM, s1>>>();
    int he_elems = in_sizes[1];
    cudaMemcpyAsync(out + ((size_t)out_size - he_elems), H_e,
                    (size_t)he_elems * sizeof(float),
                    cudaMemcpyDeviceToDevice, s1);
    cudaEventRecord(evJoin, s1);

    // s0 (critical chain): e -> Gf/Tf -> gemm1 (Bcomb)
    escale_kernel<<<E_EDGES / 8, 256>>>(H_e, p);
    convert_kernel<<<(N_NODES * (E_EDGES / 4)) / 256, 256>>>(T);
    gemm1_mma<<<NTILE1, 512, G1_SMEM>>>(adj_v);

    // join, then final GEMM
    cudaStreamWaitEvent(0, evJoin, 0);
    final_mma<<<dim3(OUT_V / 128, N_NODES / 64), 256, F_SMEM>>>(bias, out);
}